// round 9
// baseline (speedup 1.0000x reference)
#include <cuda_runtime.h>

#define MULc 16
#define S0c 8
#define S1c 8
#define SOUTc 8
#define P3c 8
#define P4c 4
#define NPATH (P3c + P4c)

#define EPB 2
#define NTHREADS 32
#define WS 200                          // floats per edge in sW (192 + pad)

__device__ __forceinline__ float4 f4fma(float s, float4 v, float4 a) {
    a.x = fmaf(s, v.x, a.x);
    a.y = fmaf(s, v.y, a.y);
    a.z = fmaf(s, v.z, a.z);
    a.w = fmaf(s, v.w, a.w);
    return a;
}

__global__ __launch_bounds__(NTHREADS) void tp_kernel(
    const float* __restrict__ x0, const int* __restrict__ i0,
    const float* __restrict__ x1, const float* __restrict__ C3,
    const float* __restrict__ C4, const int* __restrict__ p3,
    const int* __restrict__ p4, float* __restrict__ out, int E)
{
    __shared__ __align__(16) float  sW[EPB * WS];    // 1600 B
    __shared__ __align__(16) float4 sx1[EPB * S1c];  // 256 B

    const int tid  = threadIdx.x;
    const int base = blockIdx.x * EPB;
    int nE = E - base; if (nE > EPB) nE = EPB;

    // ---- stage x1 rows (2 edges x 8 float4) ----
    if (tid < nE * 8)
        sx1[tid] = reinterpret_cast<const float4*>(x1 + (size_t)base * 32)[tid];
    __syncwarp();

    // ---- W build: lanes = (half g, entry l=(i,k)) ----
    {
        const int g  = (tid >> 4) & 1;
        const int l  = tid & 15;
        const int wi = l >> 2, wk = l & 3;

        // 3-paths: 4 passes, p = 2*pass + g
        #pragma unroll
        for (int pass = 0; pass < 4; pass++) {
            const int p = pass * 2 + g;
            const int segb = __ldg(&p3[p * 3 + 1]);
            const float c0  = __ldg(&C3[p * 64 + wi * 16 + 0  + wk]);
            const float c1  = __ldg(&C3[p * 64 + wi * 16 + 4  + wk]);
            const float c2  = __ldg(&C3[p * 64 + wi * 16 + 8  + wk]);
            const float c3v = __ldg(&C3[p * 64 + wi * 16 + 12 + wk]);
            #pragma unroll
            for (int e = 0; e < EPB; e++) {
                if (e < nE) {
                    const float4 b = sx1[e * S1c + segb];
                    sW[e * WS + p * 16 + l] =
                        fmaf(b.x, c0, fmaf(b.y, c1, fmaf(b.z, c2, b.w * c3v)));
                }
            }
        }
        // 4-paths: 2 passes, q = 2*pass + g
        #pragma unroll
        for (int pass = 0; pass < 2; pass++) {
            const int q = pass * 2 + g;
            const int segb = __ldg(&p4[q * 4 + 1]);
            const int segc = __ldg(&p4[q * 4 + 2]);
            float creg[16];
            #pragma unroll
            for (int j = 0; j < 4; j++)
                #pragma unroll
                for (int m = 0; m < 4; m++)
                    creg[j * 4 + m] = __ldg(&C4[q * 256 + wi * 64 + j * 16 + m * 4 + wk]);
            #pragma unroll
            for (int e = 0; e < EPB; e++) {
                if (e < nE) {
                    const float4 b = sx1[e * S1c + segb];
                    const float4 c = sx1[e * S1c + segc];
                    float t0 = fmaf(c.x, creg[0],  fmaf(c.y, creg[1],  fmaf(c.z, creg[2],  c.w * creg[3])));
                    float t1 = fmaf(c.x, creg[4],  fmaf(c.y, creg[5],  fmaf(c.z, creg[6],  c.w * creg[7])));
                    float t2 = fmaf(c.x, creg[8],  fmaf(c.y, creg[9],  fmaf(c.z, creg[10], c.w * creg[11])));
                    float t3 = fmaf(c.x, creg[12], fmaf(c.y, creg[13], fmaf(c.z, creg[14], c.w * creg[15])));
                    sW[e * WS + (P3c + q) * 16 + l] =
                        fmaf(b.x, t0, fmaf(b.y, t1, fmaf(b.z, t2, b.w * t3)));
                }
            }
        }
    }
    __syncwarp();

    // ---- contrib: 16 lanes per edge, lane = mul index u ----
    const int eL = tid >> 4;
    const int u  = tid & 15;
    const int e  = base + eL;
    if (e >= E) return;

    // packed metadata: s | (z << 16)
    int m3[P3c], m4[P4c];
    #pragma unroll
    for (int p = 0; p < P3c; p++)
        m3[p] = __ldg(&p3[p * 3 + 0]) | (__ldg(&p3[p * 3 + 2]) << 16);
    #pragma unroll
    for (int p = 0; p < P4c; p++)
        m4[p] = __ldg(&p4[p * 4 + 0]) | (__ldg(&p4[p * 4 + 3]) << 16);

    const float4* arow = reinterpret_cast<const float4*>(
        x0 + (size_t)__ldg(&i0[e]) * (S0c * MULc * 4));
    float4* orow = reinterpret_cast<float4*>(out + (size_t)e * (SOUTc * MULc * 4));
    const float* wbase = sW + eL * WS;

    #pragma unroll
    for (int z = 0; z < SOUTc; z++) {
        float4 acc = make_float4(0.f, 0.f, 0.f, 0.f);

        #pragma unroll
        for (int pp = 0; pp < NPATH; pp++) {
            const int meta = (pp < P3c) ? m3[pp] : m4[pp - P3c];
            if ((meta >> 16) == z) {
                const int sp = meta & 0xffff;
                const float4 av = __ldg(&arow[sp * MULc + u]);
                const float4* wv = reinterpret_cast<const float4*>(wbase + pp * 16);
                acc = f4fma(av.x, wv[0], acc);
                acc = f4fma(av.y, wv[1], acc);
                acc = f4fma(av.z, wv[2], acc);
                acc = f4fma(av.w, wv[3], acc);
            }
        }
        orow[z * MULc + u] = acc;
    }
}

extern "C" void kernel_launch(void* const* d_in, const int* in_sizes, int n_in,
                              void* d_out, int out_size) {
    const float* x0 = (const float*)d_in[0];
    const int*   i0 = (const int*)d_in[1];
    const float* x1 = (const float*)d_in[2];
    const float* C3 = (const float*)d_in[3];
    const float* C4 = (const float*)d_in[4];
    const int*   p3 = (const int*)d_in[5];
    const int*   p4 = (const int*)d_in[6];

    const int E = in_sizes[1];
    const int blocks = (E + EPB - 1) / EPB;
    tp_kernel<<<blocks, NTHREADS>>>(x0, i0, x1, C3, C4, p3, p4, (float*)d_out, E);
}